// round 1
// baseline (speedup 1.0000x reference)
#include <cuda_runtime.h>
#include <cuda_bf16.h>
#include <math.h>

// Problem constants (B,T,H,A) = (64, 2048, 1024, 256)
#define BB 64
#define TT 2048
#define HH 1024
#define AA 256
#define BT (BB*TT)          // 131072 rows
#define NSPLIT 8            // T split for weighted sum

// ---------------- device scratch (no allocations allowed) ----------------
__device__ float g_vu[BT];
__device__ float g_alphas[BT];
__device__ float g_partial[NSPLIT * BB * HH];

// ---------------- helpers ----------------
__device__ __forceinline__ unsigned f2tf32(float f) {
    unsigned r;
    asm("cvt.rna.tf32.f32 %0, %1;" : "=r"(r) : "f"(f));
    return r;
}

// =====================================================================
// K1: z = X[131072,1024] @ W[1024,256]; vu[row] = sum_a tanh(z+b)*u
// CTA tile: 128 rows x 256 cols, K-step 16, 512 threads (16 warps, 4x4)
// mma.sync.aligned.m16n8k8.row.col.f32.tf32.tf32.f32
// =====================================================================
__global__ __launch_bounds__(512, 1)
void vu_kernel(const float* __restrict__ x, const float* __restrict__ W,
               const float* __restrict__ bo, const float* __restrict__ uo)
{
    __shared__ unsigned As[128 * 20];   // [row][k], stride 20 (pad, conflict-free frags)
    __shared__ unsigned Bs[16 * 260];   // [k][a],   stride 260 (pad, conflict-free frags)
    __shared__ float vu_s[128];

    const int tid  = threadIdx.x;
    const int lane = tid & 31;
    const int warp = tid >> 5;
    const int g  = lane >> 2;       // groupID
    const int tg = lane & 3;        // threadID_in_group
    const int wm = warp >> 2;       // 0..3 -> rows 32*wm
    const int wn = warp & 3;        // 0..3 -> cols 64*wn
    const int wrow = wm * 32;
    const int wcol = wn * 64;

    const size_t row0 = (size_t)blockIdx.x * 128;
    const float* xA = x + row0 * HH;

    float acc[2][8][4];
    #pragma unroll
    for (int mi = 0; mi < 2; mi++)
        #pragma unroll
        for (int ni = 0; ni < 8; ni++)
            #pragma unroll
            for (int c = 0; c < 4; c++) acc[mi][ni][c] = 0.f;

    float aReg[4], bReg[8];
    // prefetch K-stage 0
    {
        #pragma unroll
        for (int i = 0; i < 4; i++) {
            int idx = tid + i * 512;
            aReg[i] = xA[(size_t)(idx >> 4) * HH + (idx & 15)];
        }
        #pragma unroll
        for (int i = 0; i < 8; i++) {
            int idx = tid + i * 512;
            bReg[i] = W[(size_t)(idx >> 8) * AA + (idx & 255)];
        }
    }

    for (int ks = 0; ks < HH / 16; ks++) {
        // stage registers -> smem (as tf32 bit patterns)
        #pragma unroll
        for (int i = 0; i < 4; i++) {
            int idx = tid + i * 512;
            As[(idx >> 4) * 20 + (idx & 15)] = f2tf32(aReg[i]);
        }
        #pragma unroll
        for (int i = 0; i < 8; i++) {
            int idx = tid + i * 512;
            Bs[(idx >> 8) * 260 + (idx & 255)] = f2tf32(bReg[i]);
        }
        __syncthreads();

        // prefetch next K-stage into registers (overlaps with mma below)
        if (ks < HH / 16 - 1) {
            const int hb = (ks + 1) * 16;
            #pragma unroll
            for (int i = 0; i < 4; i++) {
                int idx = tid + i * 512;
                aReg[i] = xA[(size_t)(idx >> 4) * HH + hb + (idx & 15)];
            }
            #pragma unroll
            for (int i = 0; i < 8; i++) {
                int idx = tid + i * 512;
                bReg[i] = W[(size_t)(hb + (idx >> 8)) * AA + (idx & 255)];
            }
        }

        // compute: 2 k-substeps of 8
        #pragma unroll
        for (int kk = 0; kk < 16; kk += 8) {
            unsigned bf[8][2];
            #pragma unroll
            for (int ni = 0; ni < 8; ni++) {
                int n = wcol + ni * 8 + g;
                bf[ni][0] = Bs[(kk + tg)     * 260 + n];
                bf[ni][1] = Bs[(kk + tg + 4) * 260 + n];
            }
            #pragma unroll
            for (int mi = 0; mi < 2; mi++) {
                int r = wrow + mi * 16 + g;
                unsigned a0 = As[r       * 20 + kk + tg];
                unsigned a1 = As[(r + 8) * 20 + kk + tg];
                unsigned a2 = As[r       * 20 + kk + tg + 4];
                unsigned a3 = As[(r + 8) * 20 + kk + tg + 4];
                #pragma unroll
                for (int ni = 0; ni < 8; ni++) {
                    asm("mma.sync.aligned.m16n8k8.row.col.f32.tf32.tf32.f32 "
                        "{%0,%1,%2,%3},{%4,%5,%6,%7},{%8,%9},{%0,%1,%2,%3};\n"
                        : "+f"(acc[mi][ni][0]), "+f"(acc[mi][ni][1]),
                          "+f"(acc[mi][ni][2]), "+f"(acc[mi][ni][3])
                        : "r"(a0), "r"(a1), "r"(a2), "r"(a3),
                          "r"(bf[ni][0]), "r"(bf[ni][1]));
                }
            }
        }
        __syncthreads();
    }

    // epilogue: vu[row] = sum_a tanh(z + b[a]) * u[a]
    if (tid < 128) vu_s[tid] = 0.f;
    __syncthreads();
    #pragma unroll
    for (int mi = 0; mi < 2; mi++) {
        float s0 = 0.f, s1 = 0.f;
        #pragma unroll
        for (int ni = 0; ni < 8; ni++) {
            int c0 = wcol + ni * 8 + 2 * tg;
            float b0v = bo[c0], b1v = bo[c0 + 1];
            float u0v = uo[c0], u1v = uo[c0 + 1];
            s0 += tanhf(acc[mi][ni][0] + b0v) * u0v + tanhf(acc[mi][ni][1] + b1v) * u1v;
            s1 += tanhf(acc[mi][ni][2] + b0v) * u0v + tanhf(acc[mi][ni][3] + b1v) * u1v;
        }
        s0 += __shfl_xor_sync(0xffffffffu, s0, 1);
        s0 += __shfl_xor_sync(0xffffffffu, s0, 2);
        s1 += __shfl_xor_sync(0xffffffffu, s1, 1);
        s1 += __shfl_xor_sync(0xffffffffu, s1, 2);
        if (tg == 0) {
            atomicAdd(&vu_s[wrow + mi * 16 + g],     s0);
            atomicAdd(&vu_s[wrow + mi * 16 + g + 8], s1);
        }
    }
    __syncthreads();
    if (tid < 128) g_vu[row0 + tid] = vu_s[tid];
}

// =====================================================================
// K2: softmax over T per batch row. 64 CTAs x 256 threads, 8 elems/thread
// =====================================================================
__global__ void softmax_kernel()
{
    const int b = blockIdx.x, tid = threadIdx.x;
    __shared__ float red[256];
    const float* v = g_vu + b * TT;

    float loc[8];
    float m = -1e30f;
    #pragma unroll
    for (int i = 0; i < 8; i++) {
        loc[i] = v[tid + i * 256];
        m = fmaxf(m, loc[i]);
    }
    red[tid] = m;
    __syncthreads();
    for (int s = 128; s > 0; s >>= 1) {
        if (tid < s) red[tid] = fmaxf(red[tid], red[tid + s]);
        __syncthreads();
    }
    m = red[0];
    __syncthreads();

    float ssum = 0.f;
    #pragma unroll
    for (int i = 0; i < 8; i++) {
        loc[i] = expf(loc[i] - m);
        ssum += loc[i];
    }
    red[tid] = ssum;
    __syncthreads();
    for (int s = 128; s > 0; s >>= 1) {
        if (tid < s) red[tid] += red[tid + s];
        __syncthreads();
    }
    const float inv = 1.f / red[0];
    #pragma unroll
    for (int i = 0; i < 8; i++)
        g_alphas[b * TT + tid + i * 256] = loc[i] * inv;
}

// =====================================================================
// K3: partial weighted sums over T chunks. grid (NSPLIT, B), float4 loads.
// =====================================================================
__global__ void wsum_kernel(const float* __restrict__ x)
{
    const int split = blockIdx.x, b = blockIdx.y;
    const int tid = threadIdx.x;
    __shared__ float a_s[TT / NSPLIT];   // 256 alphas
    a_s[tid] = g_alphas[b * TT + split * (TT / NSPLIT) + tid];
    __syncthreads();

    const float4* xp = reinterpret_cast<const float4*>(x)
                     + (size_t)(b * TT + split * (TT / NSPLIT)) * (HH / 4) + tid;
    float4 acc = make_float4(0.f, 0.f, 0.f, 0.f);
    #pragma unroll 4
    for (int j = 0; j < TT / NSPLIT; j++) {
        const float al = a_s[j];
        const float4 xv = xp[(size_t)j * (HH / 4)];
        acc.x = fmaf(al, xv.x, acc.x);
        acc.y = fmaf(al, xv.y, acc.y);
        acc.z = fmaf(al, xv.z, acc.z);
        acc.w = fmaf(al, xv.w, acc.w);
    }
    float4* P = reinterpret_cast<float4*>(g_partial)
              + (size_t)(split * BB + b) * (HH / 4) + tid;
    *P = acc;
}

// =====================================================================
// K4: reduce the NSPLIT partials, write out [B, H+1] with ones column
// =====================================================================
__global__ void finalize_kernel(float* __restrict__ out)
{
    const int b = blockIdx.x, tid = threadIdx.x;
    for (int h = tid; h < HH; h += 256) {
        float s = 0.f;
        #pragma unroll
        for (int sp = 0; sp < NSPLIT; sp++)
            s += g_partial[(size_t)(sp * BB + b) * HH + h];
        out[b * (HH + 1) + h] = s;
    }
    if (tid == 0) out[b * (HH + 1) + HH] = 1.0f;
}

// ---------------------------------------------------------------------
extern "C" void kernel_launch(void* const* d_in, const int* in_sizes, int n_in,
                              void* d_out, int out_size)
{
    const float* x  = (const float*)d_in[0];   // [64,2048,1024]
    const float* W  = (const float*)d_in[1];   // [1024,256]
    const float* bo = (const float*)d_in[2];   // [256]
    const float* uo = (const float*)d_in[3];   // [256]
    float* out = (float*)d_out;                // [64,1025]

    vu_kernel<<<BT / 128, 512>>>(x, W, bo, uo);
    softmax_kernel<<<BB, 256>>>();
    wsum_kernel<<<dim3(NSPLIT, BB), 256>>>(x);
    finalize_kernel<<<BB, 256>>>(out);
}

// round 3
// speedup vs baseline: 2.0264x; 2.0264x over previous
#include <cuda_runtime.h>
#include <cuda_fp16.h>
#include <math.h>
#include <stdint.h>

// Problem constants (B,T,H,A) = (64, 2048, 1024, 256)
#define BB 64
#define TT 2048
#define HH 1024
#define AA 256
#define BT (BB*TT)          // 131072 rows
#define NSPLIT 32           // T split for weighted sum

#define M_CTA 128
#define KSTEP 32
#define NK (HH/KSTEP)       // 32
#define A_STRIDE 40         // halfs per A row (pad: 80B, conflict-free LDSM)
#define B_STRIDE 264        // halfs per B row (pad: 528B, conflict-free LDSM)
#define A_TILE (M_CTA*A_STRIDE)   // 5120 halfs / stage
#define B_TILE (KSTEP*B_STRIDE)   // 8448 halfs / stage

// ---------------- device scratch (no allocations allowed) ----------------
__device__ float g_vu[BT];
__device__ float g_alphas[BT];
__device__ float g_partial[NSPLIT * BB * HH];
__device__ __align__(16) __half g_Wh[HH * AA];   // W in fp16 [H][A] (k-major rows)

__device__ __forceinline__ uint32_t smem_u32(const void* p) {
    uint32_t a;
    asm("{ .reg .u64 t; cvta.to.shared.u64 t, %1; cvt.u32.u64 %0, t; }" : "=r"(a) : "l"(p));
    return a;
}

// =====================================================================
// K0: convert W [H,A] fp32 -> g_Wh fp16 (rn)
// =====================================================================
__global__ void convert_w_kernel(const float* __restrict__ W)
{
    const int i = (blockIdx.x * 256 + threadIdx.x) * 4;   // 4 elems/thread
    const float4 f = *reinterpret_cast<const float4*>(W + i);
    __half2 h0 = __floats2half2_rn(f.x, f.y);
    __half2 h1 = __floats2half2_rn(f.z, f.w);
    *reinterpret_cast<uint2*>(g_Wh + i) =
        make_uint2(*reinterpret_cast<uint32_t*>(&h0), *reinterpret_cast<uint32_t*>(&h1));
}

// =====================================================================
// K1: fp16 mma.m16n8k16 GEMM (128x256 CTA tile, K double-buffered)
//     + fused tanh/dot-u epilogue -> g_vu
// 512 threads = 16 warps (4x4); warp tile 32 rows x 64 cols.
// =====================================================================
__global__ __launch_bounds__(512, 1)
void vu_fp16_kernel(const float* __restrict__ x,
                    const float* __restrict__ bo, const float* __restrict__ uo)
{
    extern __shared__ char smem[];
    __half* As = reinterpret_cast<__half*>(smem);                    // [2][A_TILE]
    __half* Bs = reinterpret_cast<__half*>(smem) + 2 * A_TILE;       // [2][B_TILE]
    __shared__ float vu_s[M_CTA];

    const int tid  = threadIdx.x;
    const int lane = tid & 31;
    const int warp = tid >> 5;
    const int g    = lane >> 2;           // groupID
    const int tg   = lane & 3;            // thread-in-group
    const int wrow = (warp >> 2) * 32;    // 0,32,64,96
    const int wcol = (warp & 3) * 64;     // 0,64,128,192

    const uint32_t asBase = smem_u32(As);
    const uint32_t bsBase = smem_u32(Bs);

    const size_t row0 = (size_t)blockIdx.x * M_CTA;

    // ---- gmem staging mapping ----
    const int ar = tid >> 2;              // A row 0..127
    const int ak = (tid & 3) * 8;         // A k-sub 0,8,16,24
    const float* aPtr = x + (row0 + ar) * HH + ak;

    const int bk = tid >> 4;              // B k-row 0..31
    const int bn = (tid & 15) * 16;       // B n 0..240
    const __half* bPtr = g_Wh + (size_t)bk * AA + bn;

    float acc[2][8][4];
    #pragma unroll
    for (int mi = 0; mi < 2; mi++)
        #pragma unroll
        for (int ni = 0; ni < 8; ni++)
            #pragma unroll
            for (int c = 0; c < 4; c++) acc[mi][ni][c] = 0.f;

    __half2 aR[4];
    uint4 bR0, bR1;

    auto ldgA = [&](int k0) {
        const float4 f0 = *reinterpret_cast<const float4*>(aPtr + k0);
        const float4 f1 = *reinterpret_cast<const float4*>(aPtr + k0 + 4);
        aR[0] = __floats2half2_rn(f0.x, f0.y);
        aR[1] = __floats2half2_rn(f0.z, f0.w);
        aR[2] = __floats2half2_rn(f1.x, f1.y);
        aR[3] = __floats2half2_rn(f1.z, f1.w);
    };
    auto ldgB = [&](int k0) {
        const uint4* p = reinterpret_cast<const uint4*>(bPtr + (size_t)k0 * AA);
        bR0 = p[0];
        bR1 = p[1];
    };
    auto stsAB = [&](int st) {
        *reinterpret_cast<uint4*>(As + st * A_TILE + ar * A_STRIDE + ak) =
            *reinterpret_cast<uint4*>(aR);
        uint4* bq = reinterpret_cast<uint4*>(Bs + st * B_TILE + bk * B_STRIDE + bn);
        bq[0] = bR0;
        bq[1] = bR1;
    };

    auto compute = [&](int st) {
        const uint32_t aB = asBase + st * (A_TILE * 2);
        const uint32_t bB = bsBase + st * (B_TILE * 2);
        #pragma unroll
        for (int sub = 0; sub < 2; sub++) {
            // ---- A frags: 2 x ldmatrix.x4 ----
            uint32_t a[2][4];
            #pragma unroll
            for (int mi = 0; mi < 2; mi++) {
                const uint32_t addr = aB +
                    ((wrow + mi * 16 + (lane & 15)) * A_STRIDE
                     + sub * 16 + (lane >> 4) * 8) * 2;
                asm volatile("ldmatrix.sync.aligned.m8n8.x4.shared.b16 "
                             "{%0,%1,%2,%3}, [%4];"
                             : "=r"(a[mi][0]), "=r"(a[mi][1]),
                               "=r"(a[mi][2]), "=r"(a[mi][3]) : "r"(addr));
            }
            // ---- B frags: 4 x ldmatrix.x4.trans (n blocks of 16) ----
            uint32_t b[4][4];
            #pragma unroll
            for (int nb = 0; nb < 4; nb++) {
                const uint32_t addr = bB +
                    ((sub * 16 + (lane & 15)) * B_STRIDE
                     + wcol + nb * 16 + (lane >> 4) * 8) * 2;
                asm volatile("ldmatrix.sync.aligned.m8n8.x4.trans.shared.b16 "
                             "{%0,%1,%2,%3}, [%4];"
                             : "=r"(b[nb][0]), "=r"(b[nb][1]),
                               "=r"(b[nb][2]), "=r"(b[nb][3]) : "r"(addr));
            }
            // ---- 16 mma ----
            #pragma unroll
            for (int mi = 0; mi < 2; mi++)
                #pragma unroll
                for (int nb = 0; nb < 4; nb++) {
                    asm volatile(
                        "mma.sync.aligned.m16n8k16.row.col.f32.f16.f16.f32 "
                        "{%0,%1,%2,%3},{%4,%5,%6,%7},{%8,%9},{%0,%1,%2,%3};"
                        : "+f"(acc[mi][nb*2][0]), "+f"(acc[mi][nb*2][1]),
                          "+f"(acc[mi][nb*2][2]), "+f"(acc[mi][nb*2][3])
                        : "r"(a[mi][0]), "r"(a[mi][1]), "r"(a[mi][2]), "r"(a[mi][3]),
                          "r"(b[nb][0]), "r"(b[nb][1]));
                    asm volatile(
                        "mma.sync.aligned.m16n8k16.row.col.f32.f16.f16.f32 "
                        "{%0,%1,%2,%3},{%4,%5,%6,%7},{%8,%9},{%0,%1,%2,%3};"
                        : "+f"(acc[mi][nb*2+1][0]), "+f"(acc[mi][nb*2+1][1]),
                          "+f"(acc[mi][nb*2+1][2]), "+f"(acc[mi][nb*2+1][3])
                        : "r"(a[mi][0]), "r"(a[mi][1]), "r"(a[mi][2]), "r"(a[mi][3]),
                          "r"(b[nb][2]), "r"(b[nb][3]));
                }
        }
    };

    // ---- pipeline ----
    ldgA(0); ldgB(0);
    stsAB(0);
    __syncthreads();

    for (int ks = 0; ks < NK; ks++) {
        const int cur = ks & 1;
        if (ks + 1 < NK) { ldgA((ks + 1) * KSTEP); ldgB((ks + 1) * KSTEP); }
        compute(cur);
        __syncthreads();
        if (ks + 1 < NK) {
            stsAB(cur ^ 1);
            __syncthreads();
        }
    }

    // ---- epilogue: vu[row] = sum_a tanh(z + b[a]) * u[a] ----
    if (tid < M_CTA) vu_s[tid] = 0.f;
    __syncthreads();
    #pragma unroll
    for (int mi = 0; mi < 2; mi++) {
        float s0 = 0.f, s1 = 0.f;
        #pragma unroll
        for (int ni = 0; ni < 8; ni++) {
            const int c0 = wcol + ni * 8 + 2 * tg;
            const float b0v = bo[c0], b1v = bo[c0 + 1];
            const float u0v = uo[c0], u1v = uo[c0 + 1];
            s0 += tanhf(acc[mi][ni][0] + b0v) * u0v + tanhf(acc[mi][ni][1] + b1v) * u1v;
            s1 += tanhf(acc[mi][ni][2] + b0v) * u0v + tanhf(acc[mi][ni][3] + b1v) * u1v;
        }
        s0 += __shfl_xor_sync(0xffffffffu, s0, 1);
        s0 += __shfl_xor_sync(0xffffffffu, s0, 2);
        s1 += __shfl_xor_sync(0xffffffffu, s1, 1);
        s1 += __shfl_xor_sync(0xffffffffu, s1, 2);
        if (tg == 0) {
            atomicAdd(&vu_s[wrow + mi * 16 + g],     s0);
            atomicAdd(&vu_s[wrow + mi * 16 + g + 8], s1);
        }
    }
    __syncthreads();
    if (tid < M_CTA) g_vu[row0 + tid] = vu_s[tid];
}

// =====================================================================
// K2: softmax over T per batch row. 64 CTAs x 256 threads
// =====================================================================
__global__ void softmax_kernel()
{
    const int b = blockIdx.x, tid = threadIdx.x;
    __shared__ float red[256];
    const float* v = g_vu + b * TT;

    float loc[8];
    float m = -1e30f;
    #pragma unroll
    for (int i = 0; i < 8; i++) {
        loc[i] = v[tid + i * 256];
        m = fmaxf(m, loc[i]);
    }
    red[tid] = m;
    __syncthreads();
    for (int s = 128; s > 0; s >>= 1) {
        if (tid < s) red[tid] = fmaxf(red[tid], red[tid + s]);
        __syncthreads();
    }
    m = red[0];
    __syncthreads();

    float ssum = 0.f;
    #pragma unroll
    for (int i = 0; i < 8; i++) {
        loc[i] = expf(loc[i] - m);
        ssum += loc[i];
    }
    red[tid] = ssum;
    __syncthreads();
    for (int s = 128; s > 0; s >>= 1) {
        if (tid < s) red[tid] += red[tid + s];
        __syncthreads();
    }
    const float inv = 1.f / red[0];
    #pragma unroll
    for (int i = 0; i < 8; i++)
        g_alphas[b * TT + tid + i * 256] = loc[i] * inv;
}

// =====================================================================
// K3: partial weighted sums over T chunks. grid (NSPLIT, B), float4 loads.
// =====================================================================
__global__ __launch_bounds__(256)
void wsum_kernel(const float* __restrict__ x)
{
    const int split = blockIdx.x, b = blockIdx.y;
    const int tid = threadIdx.x;
    __shared__ float a_s[TT / NSPLIT];   // 64 alphas
    if (tid < TT / NSPLIT)
        a_s[tid] = g_alphas[b * TT + split * (TT / NSPLIT) + tid];
    __syncthreads();

    const float4* xp = reinterpret_cast<const float4*>(x)
                     + (size_t)(b * TT + split * (TT / NSPLIT)) * (HH / 4) + tid;
    float4 acc = make_float4(0.f, 0.f, 0.f, 0.f);
    #pragma unroll 8
    for (int j = 0; j < TT / NSPLIT; j++) {
        const float al = a_s[j];
        const float4 xv = xp[(size_t)j * (HH / 4)];
        acc.x = fmaf(al, xv.x, acc.x);
        acc.y = fmaf(al, xv.y, acc.y);
        acc.z = fmaf(al, xv.z, acc.z);
        acc.w = fmaf(al, xv.w, acc.w);
    }
    float4* P = reinterpret_cast<float4*>(g_partial)
              + (size_t)(split * BB + b) * (HH / 4) + tid;
    *P = acc;
}

// =====================================================================
// K4: reduce NSPLIT partials, write out [B, H+1] with ones column
// =====================================================================
__global__ void finalize_kernel(float* __restrict__ out)
{
    const int b = blockIdx.x, tid = threadIdx.x;
    for (int h = tid; h < HH; h += 256) {
        float s = 0.f;
        #pragma unroll
        for (int sp = 0; sp < NSPLIT; sp++)
            s += g_partial[(size_t)(sp * BB + b) * HH + h];
        out[b * (HH + 1) + h] = s;
    }
    if (tid == 0) out[b * (HH + 1) + HH] = 1.0f;
}

// ---------------------------------------------------------------------
extern "C" void kernel_launch(void* const* d_in, const int* in_sizes, int n_in,
                              void* d_out, int out_size)
{
    const float* x  = (const float*)d_in[0];   // [64,2048,1024]
    const float* W  = (const float*)d_in[1];   // [1024,256]
    const float* bo = (const float*)d_in[2];   // [256]
    const float* uo = (const float*)d_in[3];   // [256]
    float* out = (float*)d_out;                // [64,1025]

    const int DSMEM = (2 * A_TILE + 2 * B_TILE) * 2;   // 54272 bytes
    static bool attr_done = false;
    if (!attr_done) {
        cudaFuncSetAttribute(vu_fp16_kernel,
                             cudaFuncAttributeMaxDynamicSharedMemorySize, DSMEM);
        attr_done = true;
    }

    convert_w_kernel<<<(HH * AA) / (256 * 4), 256>>>(W);
    vu_fp16_kernel<<<BT / M_CTA, 512, DSMEM>>>(x, bo, uo);
    softmax_kernel<<<BB, 256>>>();
    wsum_kernel<<<dim3(NSPLIT, BB), 256>>>(x);
    finalize_kernel<<<BB, 256>>>(out);
}